// round 10
// baseline (speedup 1.0000x reference)
#include <cuda_runtime.h>
#include <cuda_bf16.h>
#include <cstdint>

#define BATCH 4
#define CCH   256
#define DQK   32
#define NTOK  4096

__device__ __nv_bfloat16 g_q[BATCH * NTOK * DQK];
__device__ __nv_bfloat16 g_k[BATCH * NTOK * DQK];
__device__ uint8_t       g_v[BATCH * CCH * NTOK];   // fp8 e4m3, channel-major

__device__ __forceinline__ uint32_t smem_u32(const void* p) {
    return (uint32_t)__cvta_generic_to_shared(p);
}
__device__ __forceinline__ void cp16(uint32_t dst, const void* src) {
    asm volatile("cp.async.cg.shared.global [%0], [%1], 16;\n" :: "r"(dst), "l"(src));
}
__device__ __forceinline__ void cp_commit() { asm volatile("cp.async.commit_group;\n"); }
template <int N> __device__ __forceinline__ void cp_wait() {
    asm volatile("cp.async.wait_group %0;\n" :: "n"(N));
}
__device__ __forceinline__ void ldsm_x4(uint32_t* r, uint32_t a) {
    asm volatile("ldmatrix.sync.aligned.m8n8.x4.shared.b16 {%0,%1,%2,%3}, [%4];\n"
                 : "=r"(r[0]), "=r"(r[1]), "=r"(r[2]), "=r"(r[3]) : "r"(a));
}
__device__ __forceinline__ void ldsm_x4_t(uint32_t* r, uint32_t a) {
    asm volatile("ldmatrix.sync.aligned.m8n8.x4.trans.shared.b16 {%0,%1,%2,%3}, [%4];\n"
                 : "=r"(r[0]), "=r"(r[1]), "=r"(r[2]), "=r"(r[3]) : "r"(a));
}
__device__ __forceinline__ void mma_bf16(float* c, const uint32_t* a, const uint32_t* b) {
    asm volatile(
        "mma.sync.aligned.m16n8k16.row.col.f32.bf16.bf16.f32 "
        "{%0,%1,%2,%3}, {%4,%5,%6,%7}, {%8,%9}, {%0,%1,%2,%3};\n"
        : "+f"(c[0]), "+f"(c[1]), "+f"(c[2]), "+f"(c[3])
        : "r"(a[0]), "r"(a[1]), "r"(a[2]), "r"(a[3]), "r"(b[0]), "r"(b[1]));
}
__device__ __forceinline__ void mma_fp8(float* c, const uint32_t* a, const uint32_t* b) {
    asm volatile(
        "mma.sync.aligned.m16n8k32.row.col.f32.e4m3.e4m3.f32 "
        "{%0,%1,%2,%3}, {%4,%5,%6,%7}, {%8,%9}, {%0,%1,%2,%3};\n"
        : "+f"(c[0]), "+f"(c[1]), "+f"(c[2]), "+f"(c[3])
        : "r"(a[0]), "r"(a[1]), "r"(a[2]), "r"(a[3]), "r"(b[0]), "r"(b[1]));
}
// d = {hi, lo}: first PTX source -> upper byte
__device__ __forceinline__ uint16_t pack_e4m3(float lo, float hi) {
    uint16_t u;
    asm("cvt.rn.satfinite.e4m3x2.f32 %0, %1, %2;" : "=h"(u) : "f"(hi), "f"(lo));
    return u;
}
__device__ __forceinline__ uint8_t f8_e4m3(float v) {
    uint16_t u;
    asm("cvt.rn.satfinite.e4m3x2.f32 %0, %1, %2;" : "=h"(u) : "f"(0.f), "f"(v));
    return (uint8_t)u;
}
__device__ __forceinline__ float ex2f(float x) {
    float y; asm("ex2.approx.ftz.f32 %0, %1;" : "=f"(y) : "f"(x)); return y;
}

// ===================== projection kernel =====================
#define PROJ_SMEM (32768 + 16384 + 2560)

__global__ void __launch_bounds__(256, 2)
proj_kernel(const float* __restrict__ zin, const float* __restrict__ xin,
            const float* __restrict__ yin,
            const float* __restrict__ Wq, const float* __restrict__ bq,
            const float* __restrict__ Wk, const float* __restrict__ bk,
            const float* __restrict__ Wv, const float* __restrict__ bv) {
    extern __shared__ char smem[];
    char* sA  = smem;           // [c=256][128B] bf16 swizzled
    char* sW  = smem + 32768;   // [d=32][512B]  bf16 swizzled
    char* sSt = smem + 49152;   // v staging [32 d][80B] fp8

    const int sel = blockIdx.z, b = blockIdx.y, n0 = blockIdx.x * 64;
    const int tid = threadIdx.x, l = tid & 31, wid = tid >> 5;
    const int wr = wid >> 1, wc = wid & 1;

    const float* src  = (sel == 0) ? xin : ((sel == 1) ? yin : zin);
    const float* W    = (sel == 0) ? Wq  : ((sel == 1) ? Wk  : Wv);
    const float* bias = (sel == 0) ? bq  : ((sel == 1) ? bk  : bv);
    const int nchunks = (sel == 2) ? 8 : 1;
    const float osc   = (sel == 0) ? 1.44269504f : 1.0f;   // fold log2(e) into q

#pragma unroll
    for (int j = 0; j < 16; ++j) {
        int id = j * 256 + tid;
        int c = id >> 4, nq = id & 15;
        float4 f = *(const float4*)(src + ((size_t)(b * CCH + c) * NTOK + n0 + nq * 4));
        int nb = nq * 8;
        int phys = c * 128 + ((((nb & ~15) ^ ((c & 7) << 4))) | (nb & 15));
        *(__nv_bfloat162*)(sA + phys)     = __floats2bfloat162_rn(f.x, f.y);
        *(__nv_bfloat162*)(sA + phys + 4) = __floats2bfloat162_rn(f.z, f.w);
    }

    for (int oc = 0; oc < nchunks; ++oc) {
        __syncthreads();
#pragma unroll
        for (int j = 0; j < 8; ++j) {
            int id = j * 256 + tid;
            int dd = id >> 6, cq = id & 63;
            float4 f = *(const float4*)(W + (size_t)(oc * 32 + dd) * CCH + cq * 4);
            int cb = cq * 8;
            int phys = dd * 512 + ((((cb & ~15) ^ ((dd & 7) << 4))) | (cb & 15));
            *(__nv_bfloat162*)(sW + phys)     = __floats2bfloat162_rn(f.x, f.y);
            *(__nv_bfloat162*)(sW + phys + 4) = __floats2bfloat162_rn(f.z, f.w);
        }
        __syncthreads();

        float acc[2][4] = {{0.f,0.f,0.f,0.f},{0.f,0.f,0.f,0.f}};
#pragma unroll
        for (int ks = 0; ks < 16; ++ks) {
            uint32_t aA[4], bw[4];
            int crow = ks * 16 + (l & 7) + ((l & 16) ? 8 : 0);
            int nb   = wr * 32 + ((l & 8) ? 16 : 0);
            ldsm_x4_t(aA, smem_u32(sA + crow * 128 + (nb ^ ((crow & 7) << 4))));
            int dd = wc * 16 + (l & 7) + ((l & 16) ? 8 : 0);
            int cb = ks * 32 + ((l & 8) ? 16 : 0);
            ldsm_x4(bw, smem_u32(sW + dd * 512 + (cb ^ ((dd & 7) << 4))));
            mma_bf16(acc[0], aA, bw);
            mma_bf16(acc[1], aA, bw + 2);
        }

        int nloc = wr * 16 + (l >> 2);
        int dloc = wc * 16 + 2 * (l & 3);

        if (sel != 2) {
            __nv_bfloat16* dst = (sel == 0) ? g_q : g_k;
#pragma unroll
            for (int t = 0; t < 2; ++t) {
                int d = dloc + t * 8;
                float b0 = bias[d], b1 = bias[d + 1];
                *(__nv_bfloat162*)(dst + ((size_t)(b * NTOK + n0 + nloc) * DQK + d)) =
                    __floats2bfloat162_rn((acc[t][0] + b0) * osc, (acc[t][1] + b1) * osc);
                *(__nv_bfloat162*)(dst + ((size_t)(b * NTOK + n0 + nloc + 8) * DQK + d)) =
                    __floats2bfloat162_rn((acc[t][2] + b0) * osc, (acc[t][3] + b1) * osc);
            }
        } else {
            // stage transposed [d][tok] fp8 (80B stride), then coalesced STG
#pragma unroll
            for (int t = 0; t < 2; ++t) {
                int d = dloc + t * 8;
                float b0 = bias[oc * 32 + d], b1 = bias[oc * 32 + d + 1];
                *(uint8_t*)(sSt + d * 80 + nloc)           = f8_e4m3(acc[t][0] + b0);
                *(uint8_t*)(sSt + (d + 1) * 80 + nloc)     = f8_e4m3(acc[t][1] + b1);
                *(uint8_t*)(sSt + d * 80 + nloc + 8)       = f8_e4m3(acc[t][2] + b0);
                *(uint8_t*)(sSt + (d + 1) * 80 + nloc + 8) = f8_e4m3(acc[t][3] + b1);
            }
            __syncthreads();
            int d = tid >> 3, k8 = (tid & 7) * 8;
            uint2 v = *(uint2*)(sSt + d * 80 + k8);
            *(uint2*)(g_v + ((size_t)(b * CCH + oc * 32 + d) * NTOK + n0 + k8)) = v;
        }
    }
}

// ===================== flash attention kernel =====================
// M=128 tile, 512 thr, Nk=64. QK bf16 HMMA (key-split 4 ways); P in fp8 smem
// (80B stride, conflict-free LDS.32 frags); PV via fp8 m16n8k32 MMA.
// smem: Q 8K | K 3x4K | V 3x20K | P 2x10K | sums 2K = 102KB
#define SQ_OFF 0
#define SK_OFF 8192
#define SV_OFF 20480
#define SP_OFF 81920
#define SS_OFF 102400
#define FLASH_SMEM 104448

__device__ __forceinline__ void load_kv(char* smem, int st,
                                        const __nv_bfloat16* kp,
                                        const uint8_t* vp,
                                        int n0k, int tid) {
    char* sK = smem + SK_OFF + st * 4096;
    char* sV = smem + SV_OFF + st * 20480;
    if (tid < 256) {   // K: 64 rows x 64B bf16 swizzled
        int n = tid >> 2, cc = tid & 3;
        cp16(smem_u32(sK + n * 64 + ((cc * 16) ^ (((n >> 1) & 3) << 4))),
             kp + (size_t)(n0k + n) * DQK + cc * 8);
    }
#pragma unroll
    for (int j = 0; j < 2; ++j) {   // V: 256 ch rows x 64B fp8, 80B stride
        int id = j * 512 + tid;
        int ch = id >> 2, c16 = id & 3;
        cp16(smem_u32(sV + ch * 80 + c16 * 16),
             vp + (size_t)ch * NTOK + n0k + c16 * 16);
    }
}

// QK 16 keys/warp (bf16), exp, fp8 P store
__device__ __forceinline__ void qk_store(char* smem, int stage, char* sPdst,
                                         const uint32_t (&aq)[2][2][4],
                                         float (&li)[2][2],
                                         int wr, int wkc, int l) {
    char* cK = smem + SK_OFF + stage * 4096;
#pragma unroll
    for (int nt = 0; nt < 2; ++nt) {
        uint32_t bk[4];
        int n  = wkc * 16 + nt * 8 + (l & 7);
        int cb = (l >> 3) << 4;
        ldsm_x4(bk, smem_u32(cK + n * 64 + (cb ^ (((n >> 1) & 3) << 4))));
#pragma unroll
        for (int mt = 0; mt < 2; ++mt) {
            float s[4] = {0.f, 0.f, 0.f, 0.f};
            mma_bf16(s, aq[mt][0], bk);
            mma_bf16(s, aq[mt][1], bk + 2);
            s[0] = ex2f(s[0]); s[1] = ex2f(s[1]);
            s[2] = ex2f(s[2]); s[3] = ex2f(s[3]);
            li[mt][0] += s[0] + s[1];
            li[mt][1] += s[2] + s[3];
            int R0 = wr * 32 + mt * 16 + (l >> 2), R1 = R0 + 8;
            int k0 = wkc * 16 + nt * 8 + 2 * (l & 3);
            *(uint16_t*)(sPdst + R0 * 80 + k0) = pack_e4m3(s[0], s[1]);
            *(uint16_t*)(sPdst + R1 * 80 + k0) = pack_e4m3(s[2], s[3]);
        }
    }
}

__global__ void __launch_bounds__(512, 1)
flash_kernel(const float* __restrict__ zin, float* __restrict__ out) {
    extern __shared__ char smem[];
    char*  sQ   = smem + SQ_OFF;
    float* sSum = (float*)(smem + SS_OFF);

    const int b = blockIdx.y, m0 = blockIdx.x * 128;
    const int tid = threadIdx.x, l = tid & 31, wid = tid >> 5;
    const int wr  = wid >> 2;      // 0..3 : 32-query rowgroup
    const int wkc = wid & 3;       // 0..3 : keygroup (QK) / chgroup (PV)

    const __nv_bfloat16* qp = g_q + (size_t)b * NTOK * DQK;
    const __nv_bfloat16* kp = g_k + (size_t)b * NTOK * DQK;
    const uint8_t*       vp = g_v + (size_t)b * CCH * NTOK;

    {   // Q tile: 128 rows x 64B
        int m = tid >> 2, cc = tid & 3;
        cp16(smem_u32(sQ + m * 64 + ((cc * 16) ^ (((m >> 1) & 3) << 4))),
             qp + (size_t)(m0 + m) * DQK + cc * 8);
    }
    load_kv(smem, 0, kp, vp, 0, tid);
    cp_commit();                    // G0: Q + stage0
    load_kv(smem, 1, kp, vp, 64, tid);
    cp_commit();                    // G1: stage1
    cp_wait<1>();                   // G0 done
    __syncthreads();

    uint32_t aq[2][2][4];
#pragma unroll
    for (int mt = 0; mt < 2; ++mt)
#pragma unroll
        for (int ks = 0; ks < 2; ++ks) {
            int row = wr * 32 + mt * 16 + (l & 15);
            int cb  = ks * 32 + ((l & 16) ? 16 : 0);
            ldsm_x4(aq[mt][ks], smem_u32(sQ + row * 64 + (cb ^ (((row >> 1) & 3) << 4))));
        }

    float o[2][8][4];
#pragma unroll
    for (int mt = 0; mt < 2; ++mt)
#pragma unroll
        for (int nt = 0; nt < 8; ++nt) { o[mt][nt][0]=0.f; o[mt][nt][1]=0.f; o[mt][nt][2]=0.f; o[mt][nt][3]=0.f; }
    float li[2][2] = {{0.f, 0.f}, {0.f, 0.f}};

    // QK(0) into P buf0
    qk_store(smem, 0, smem + SP_OFF, aq, li, wr, wkc, l);

#pragma unroll 1
    for (int it = 0; it < 64; ++it) {
        __syncthreads();   // P(it) visible; V stage(it) ready; old buffers free

        if (it + 2 < 64) load_kv(smem, (it + 2) % 3, kp, vp, (it + 2) * 64, tid);
        cp_commit();

        char* cV  = smem + SV_OFF + (it % 3) * 20480;
        char* sPc = smem + SP_OFF + (it & 1) * 10240;

        // ---- PV(it): fp8, 32 q-rows x 64 ch per warp ----
        uint32_t pA[2][2][4];   // [mt][ks][reg]
#pragma unroll
        for (int mt = 0; mt < 2; ++mt)
#pragma unroll
            for (int ks = 0; ks < 2; ++ks) {
                int r = wr * 32 + mt * 16 + (l >> 2);
                int base = ks * 32 + 4 * (l & 3);
                pA[mt][ks][0] = *(uint32_t*)(sPc + r * 80 + base);
                pA[mt][ks][1] = *(uint32_t*)(sPc + (r + 8) * 80 + base);
                pA[mt][ks][2] = *(uint32_t*)(sPc + r * 80 + base + 16);
                pA[mt][ks][3] = *(uint32_t*)(sPc + (r + 8) * 80 + base + 16);
            }
#pragma unroll
        for (int nt = 0; nt < 8; ++nt) {
            int chr = wkc * 64 + nt * 8 + (l >> 2);
            uint32_t bv0[2], bv1[2];
            bv0[0] = *(uint32_t*)(cV + chr * 80 + 4 * (l & 3));
            bv0[1] = *(uint32_t*)(cV + chr * 80 + 16 + 4 * (l & 3));
            bv1[0] = *(uint32_t*)(cV + chr * 80 + 32 + 4 * (l & 3));
            bv1[1] = *(uint32_t*)(cV + chr * 80 + 48 + 4 * (l & 3));
#pragma unroll
            for (int mt = 0; mt < 2; ++mt) {
                mma_fp8(o[mt][nt], pA[mt][0], bv0);
                mma_fp8(o[mt][nt], pA[mt][1], bv1);
            }
        }

        cp_wait<1>();      // stage(it+1) fully arrived
        if (it + 1 < 64)
            qk_store(smem, (it + 1) % 3, smem + SP_OFF + ((it + 1) & 1) * 10240,
                     aq, li, wr, wkc, l);
    }

    // ---- epilogue: cross-warp row-sum reduction ----
#pragma unroll
    for (int mt = 0; mt < 2; ++mt)
#pragma unroll
        for (int h = 0; h < 2; ++h) {
            li[mt][h] += __shfl_xor_sync(0xffffffffu, li[mt][h], 1);
            li[mt][h] += __shfl_xor_sync(0xffffffffu, li[mt][h], 2);
        }
    if ((l & 3) == 0) {
#pragma unroll
        for (int mt = 0; mt < 2; ++mt)
#pragma unroll
            for (int h = 0; h < 2; ++h)
                sSum[(wr * 32 + mt * 16 + h * 8 + (l >> 2)) * 4 + wkc] = li[mt][h];
    }
    __syncthreads();

#pragma unroll
    for (int mt = 0; mt < 2; ++mt) {
        int r0 = wr * 32 + mt * 16 + (l >> 2);
        float4 s0 = *(float4*)(sSum + r0 * 4);
        float4 s1 = *(float4*)(sSum + (r0 + 8) * 4);
        float i0 = 1.f / (s0.x + s0.y + s0.z + s0.w);
        float i1 = 1.f / (s1.x + s1.y + s1.z + s1.w);
        int tok = m0 + r0;
#pragma unroll
        for (int nt = 0; nt < 8; ++nt) {
            int ch = wkc * 64 + nt * 8 + 2 * (l & 3);
            size_t base0 = ((size_t)(b * CCH + ch)) * NTOK + tok;
            size_t base1 = base0 + NTOK;
            out[base0]     = zin[base0]     + o[mt][nt][0] * i0;
            out[base1]     = zin[base1]     + o[mt][nt][1] * i0;
            out[base0 + 8] = zin[base0 + 8] + o[mt][nt][2] * i1;
            out[base1 + 8] = zin[base1 + 8] + o[mt][nt][3] * i1;
        }
    }
}

extern "C" void kernel_launch(void* const* d_in, const int* in_sizes, int n_in,
                              void* d_out, int out_size) {
    const float* z  = (const float*)d_in[0];
    const float* x  = (const float*)d_in[1];
    const float* y  = (const float*)d_in[2];
    const float* Wq = (const float*)d_in[3];
    const float* bq = (const float*)d_in[4];
    const float* Wk = (const float*)d_in[5];
    const float* bk = (const float*)d_in[6];
    const float* Wv = (const float*)d_in[7];
    const float* bv = (const float*)d_in[8];
    float* out = (float*)d_out;

    cudaFuncSetAttribute(proj_kernel, cudaFuncAttributeMaxDynamicSharedMemorySize,
                         PROJ_SMEM);
    cudaFuncSetAttribute(flash_kernel, cudaFuncAttributeMaxDynamicSharedMemorySize,
                         FLASH_SMEM);

    proj_kernel<<<dim3(64, 4, 3), 256, PROJ_SMEM>>>(z, x, y, Wq, bq, Wk, bk, Wv, bv);
    flash_kernel<<<dim3(32, 4), 512, FLASH_SMEM>>>(z, out);
}

// round 11
// speedup vs baseline: 1.1052x; 1.1052x over previous
#include <cuda_runtime.h>
#include <cuda_bf16.h>
#include <cstdint>

#define BATCH 4
#define CCH   256
#define DQK   32
#define NTOK  4096

__device__ __nv_bfloat16 g_q[BATCH * NTOK * DQK];
__device__ __nv_bfloat16 g_k[BATCH * NTOK * DQK];
__device__ uint8_t       g_v[BATCH * CCH * NTOK];   // fp8, tile-blocked [B][64][256][64]

__device__ __forceinline__ uint32_t smem_u32(const void* p) {
    return (uint32_t)__cvta_generic_to_shared(p);
}
__device__ __forceinline__ void cp16(uint32_t dst, const void* src) {
    asm volatile("cp.async.cg.shared.global [%0], [%1], 16;\n" :: "r"(dst), "l"(src));
}
__device__ __forceinline__ void cp_commit() { asm volatile("cp.async.commit_group;\n"); }
template <int N> __device__ __forceinline__ void cp_wait() {
    asm volatile("cp.async.wait_group %0;\n" :: "n"(N));
}
__device__ __forceinline__ void ldsm_x4(uint32_t* r, uint32_t a) {
    asm volatile("ldmatrix.sync.aligned.m8n8.x4.shared.b16 {%0,%1,%2,%3}, [%4];\n"
                 : "=r"(r[0]), "=r"(r[1]), "=r"(r[2]), "=r"(r[3]) : "r"(a));
}
__device__ __forceinline__ void ldsm_x4_t(uint32_t* r, uint32_t a) {
    asm volatile("ldmatrix.sync.aligned.m8n8.x4.trans.shared.b16 {%0,%1,%2,%3}, [%4];\n"
                 : "=r"(r[0]), "=r"(r[1]), "=r"(r[2]), "=r"(r[3]) : "r"(a));
}
__device__ __forceinline__ void mma_bf16(float* c, const uint32_t* a, const uint32_t* b) {
    asm volatile(
        "mma.sync.aligned.m16n8k16.row.col.f32.bf16.bf16.f32 "
        "{%0,%1,%2,%3}, {%4,%5,%6,%7}, {%8,%9}, {%0,%1,%2,%3};\n"
        : "+f"(c[0]), "+f"(c[1]), "+f"(c[2]), "+f"(c[3])
        : "r"(a[0]), "r"(a[1]), "r"(a[2]), "r"(a[3]), "r"(b[0]), "r"(b[1]));
}
__device__ __forceinline__ void mma_fp8(float* c, const uint32_t* a, const uint32_t* b) {
    asm volatile(
        "mma.sync.aligned.m16n8k32.row.col.f32.e4m3.e4m3.f32 "
        "{%0,%1,%2,%3}, {%4,%5,%6,%7}, {%8,%9}, {%0,%1,%2,%3};\n"
        : "+f"(c[0]), "+f"(c[1]), "+f"(c[2]), "+f"(c[3])
        : "r"(a[0]), "r"(a[1]), "r"(a[2]), "r"(a[3]), "r"(b[0]), "r"(b[1]));
}
__device__ __forceinline__ uint16_t pack_e4m3(float lo, float hi) {
    uint16_t u;
    asm("cvt.rn.satfinite.e4m3x2.f32 %0, %1, %2;" : "=h"(u) : "f"(hi), "f"(lo));
    return u;
}
__device__ __forceinline__ uint8_t f8_e4m3(float v) {
    uint16_t u;
    asm("cvt.rn.satfinite.e4m3x2.f32 %0, %1, %2;" : "=h"(u) : "f"(0.f), "f"(v));
    return (uint8_t)u;
}
__device__ __forceinline__ float ex2f(float x) {
    float y; asm("ex2.approx.ftz.f32 %0, %1;" : "=f"(y) : "f"(x)); return y;
}

// ===================== projection kernel =====================
#define PROJ_SMEM (32768 + 16384 + 2560)

__global__ void __launch_bounds__(256, 2)
proj_kernel(const float* __restrict__ zin, const float* __restrict__ xin,
            const float* __restrict__ yin,
            const float* __restrict__ Wq, const float* __restrict__ bq,
            const float* __restrict__ Wk, const float* __restrict__ bk,
            const float* __restrict__ Wv, const float* __restrict__ bv) {
    extern __shared__ char smem[];
    char* sA  = smem;           // [c=256][128B] bf16 swizzled
    char* sW  = smem + 32768;   // [d=32][512B]  bf16 swizzled
    char* sSt = smem + 49152;   // v staging [32 d][80B] fp8

    const int sel = blockIdx.z, b = blockIdx.y, n0 = blockIdx.x * 64;
    const int tid = threadIdx.x, l = tid & 31, wid = tid >> 5;
    const int wr = wid >> 1, wc = wid & 1;

    const float* src  = (sel == 0) ? xin : ((sel == 1) ? yin : zin);
    const float* W    = (sel == 0) ? Wq  : ((sel == 1) ? Wk  : Wv);
    const float* bias = (sel == 0) ? bq  : ((sel == 1) ? bk  : bv);
    const int nchunks = (sel == 2) ? 8 : 1;
    const float osc   = (sel == 0) ? 1.44269504f : 1.0f;   // fold log2(e) into q

#pragma unroll
    for (int j = 0; j < 16; ++j) {
        int id = j * 256 + tid;
        int c = id >> 4, nq = id & 15;
        float4 f = *(const float4*)(src + ((size_t)(b * CCH + c) * NTOK + n0 + nq * 4));
        int nb = nq * 8;
        int phys = c * 128 + ((((nb & ~15) ^ ((c & 7) << 4))) | (nb & 15));
        *(__nv_bfloat162*)(sA + phys)     = __floats2bfloat162_rn(f.x, f.y);
        *(__nv_bfloat162*)(sA + phys + 4) = __floats2bfloat162_rn(f.z, f.w);
    }

    for (int oc = 0; oc < nchunks; ++oc) {
        __syncthreads();
#pragma unroll
        for (int j = 0; j < 8; ++j) {
            int id = j * 256 + tid;
            int dd = id >> 6, cq = id & 63;
            float4 f = *(const float4*)(W + (size_t)(oc * 32 + dd) * CCH + cq * 4);
            int cb = cq * 8;
            int phys = dd * 512 + ((((cb & ~15) ^ ((dd & 7) << 4))) | (cb & 15));
            *(__nv_bfloat162*)(sW + phys)     = __floats2bfloat162_rn(f.x, f.y);
            *(__nv_bfloat162*)(sW + phys + 4) = __floats2bfloat162_rn(f.z, f.w);
        }
        __syncthreads();

        float acc[2][4] = {{0.f,0.f,0.f,0.f},{0.f,0.f,0.f,0.f}};
#pragma unroll
        for (int ks = 0; ks < 16; ++ks) {
            uint32_t aA[4], bw[4];
            int crow = ks * 16 + (l & 7) + ((l & 16) ? 8 : 0);
            int nb   = wr * 32 + ((l & 8) ? 16 : 0);
            ldsm_x4_t(aA, smem_u32(sA + crow * 128 + (nb ^ ((crow & 7) << 4))));
            int dd = wc * 16 + (l & 7) + ((l & 16) ? 8 : 0);
            int cb = ks * 32 + ((l & 8) ? 16 : 0);
            ldsm_x4(bw, smem_u32(sW + dd * 512 + (cb ^ ((dd & 7) << 4))));
            mma_bf16(acc[0], aA, bw);
            mma_bf16(acc[1], aA, bw + 2);
        }

        int nloc = wr * 16 + (l >> 2);
        int dloc = wc * 16 + 2 * (l & 3);

        if (sel != 2) {
            __nv_bfloat16* dst = (sel == 0) ? g_q : g_k;
#pragma unroll
            for (int t = 0; t < 2; ++t) {
                int d = dloc + t * 8;
                float b0 = bias[d], b1 = bias[d + 1];
                *(__nv_bfloat162*)(dst + ((size_t)(b * NTOK + n0 + nloc) * DQK + d)) =
                    __floats2bfloat162_rn((acc[t][0] + b0) * osc, (acc[t][1] + b1) * osc);
                *(__nv_bfloat162*)(dst + ((size_t)(b * NTOK + n0 + nloc + 8) * DQK + d)) =
                    __floats2bfloat162_rn((acc[t][2] + b0) * osc, (acc[t][3] + b1) * osc);
            }
        } else {
            // stage transposed [d][tok] fp8 (80B stride), then contiguous STG
#pragma unroll
            for (int t = 0; t < 2; ++t) {
                int d = dloc + t * 8;
                float b0 = bias[oc * 32 + d], b1 = bias[oc * 32 + d + 1];
                *(uint8_t*)(sSt + d * 80 + nloc)           = f8_e4m3(acc[t][0] + b0);
                *(uint8_t*)(sSt + (d + 1) * 80 + nloc)     = f8_e4m3(acc[t][1] + b1);
                *(uint8_t*)(sSt + d * 80 + nloc + 8)       = f8_e4m3(acc[t][2] + b0);
                *(uint8_t*)(sSt + (d + 1) * 80 + nloc + 8) = f8_e4m3(acc[t][3] + b1);
            }
            __syncthreads();
            int d = tid >> 3, k8 = (tid & 7) * 8;
            uint2 v = *(uint2*)(sSt + d * 80 + k8);
            // tile-blocked: [b][tile=blockIdx.x][ch][key]
            *(uint2*)(g_v + ((((size_t)b * 64 + blockIdx.x) * 256) + oc * 32 + d) * 64 + k8) = v;
        }
    }
}

// ===================== flash attention kernel =====================
// M=128 tile, 512 thr, Nk=64, 4-stage ring. QK bf16 (key-split 4 ways);
// P fp8 in swizzled 64B rows (ldmatrix A-frags); V fp8 tile-blocked global,
// swizzled 64B ch-rows in smem (ldmatrix B-frags); PV fp8 m16n8k32.
// smem: Q 8K | K 4x4K | V 4x16K | P 2x8K | sums 2K = 106KB
#define SQ_OFF 0
#define SK_OFF 8192
#define SV_OFF 24576
#define SP_OFF 90112
#define SS_OFF 106496
#define FLASH_SMEM 108544

__device__ __forceinline__ void load_kv(char* smem, int st,
                                        const __nv_bfloat16* kp,
                                        const uint8_t* vp,
                                        int n0k, int tid) {
    char* sK = smem + SK_OFF + st * 4096;
    char* sV = smem + SV_OFF + st * 16384;
    if (tid < 256) {   // K: 64 rows x 64B bf16 swizzled
        int n = tid >> 2, cc = tid & 3;
        cp16(smem_u32(sK + n * 64 + ((cc * 16) ^ (((n >> 1) & 3) << 4))),
             kp + (size_t)(n0k + n) * DQK + cc * 8);
    }
#pragma unroll
    for (int j = 0; j < 2; ++j) {   // V: 256 ch rows x 64B fp8, swizzled; global contiguous
        int id = j * 512 + tid;
        int ch = id >> 2, c16 = id & 3;
        cp16(smem_u32(sV + ch * 64 + ((c16 * 16) ^ (((ch >> 1) & 3) << 4))),
             vp + ((size_t)n0k << 8) + (size_t)id * 16);
    }
}

// QK 16 keys/warp (bf16), exp, fp8 P store into swizzled 64B rows
__device__ __forceinline__ void qk_store(char* smem, int stage, char* sPdst,
                                         const uint32_t (&aq)[2][2][4],
                                         float (&li)[2][2],
                                         int wr, int wkc, int l) {
    char* cK = smem + SK_OFF + stage * 4096;
#pragma unroll
    for (int nt = 0; nt < 2; ++nt) {
        uint32_t bk[4];
        int n  = wkc * 16 + nt * 8 + (l & 7);
        int cb = (l >> 3) << 4;
        ldsm_x4(bk, smem_u32(cK + n * 64 + (cb ^ (((n >> 1) & 3) << 4))));
#pragma unroll
        for (int mt = 0; mt < 2; ++mt) {
            float s[4] = {0.f, 0.f, 0.f, 0.f};
            mma_bf16(s, aq[mt][0], bk);
            mma_bf16(s, aq[mt][1], bk + 2);
            s[0] = ex2f(s[0]); s[1] = ex2f(s[1]);
            s[2] = ex2f(s[2]); s[3] = ex2f(s[3]);
            li[mt][0] += s[0] + s[1];
            li[mt][1] += s[2] + s[3];
            int R0 = wr * 32 + mt * 16 + (l >> 2), R1 = R0 + 8;
            int k0 = wkc * 16 + nt * 8 + 2 * (l & 3);
            int o0 = R0 * 64 + ((((k0 & ~15) ^ (((R0 >> 1) & 3) << 4))) | (k0 & 15));
            int o1 = R1 * 64 + ((((k0 & ~15) ^ (((R1 >> 1) & 3) << 4))) | (k0 & 15));
            *(uint16_t*)(sPdst + o0) = pack_e4m3(s[0], s[1]);
            *(uint16_t*)(sPdst + o1) = pack_e4m3(s[2], s[3]);
        }
    }
}

__global__ void __launch_bounds__(512, 1)
flash_kernel(const float* __restrict__ zin, float* __restrict__ out) {
    extern __shared__ char smem[];
    char*  sQ   = smem + SQ_OFF;
    float* sSum = (float*)(smem + SS_OFF);

    const int b = blockIdx.y, m0 = blockIdx.x * 128;
    const int tid = threadIdx.x, l = tid & 31, wid = tid >> 5;
    const int wr  = wid >> 2;      // 0..3 : 32-query rowgroup
    const int wkc = wid & 3;       // 0..3 : keygroup (QK) / chgroup (PV)

    const __nv_bfloat16* qp = g_q + (size_t)b * NTOK * DQK;
    const __nv_bfloat16* kp = g_k + (size_t)b * NTOK * DQK;
    const uint8_t*       vp = g_v + (size_t)b * CCH * NTOK;

    {   // Q tile: 128 rows x 64B
        int m = tid >> 2, cc = tid & 3;
        cp16(smem_u32(sQ + m * 64 + ((cc * 16) ^ (((m >> 1) & 3) << 4))),
             qp + (size_t)(m0 + m) * DQK + cc * 8);
    }
    load_kv(smem, 0, kp, vp, 0, tid);
    cp_commit();                    // G0: Q + stage0
    load_kv(smem, 1, kp, vp, 64, tid);
    cp_commit();                    // G1
    load_kv(smem, 2, kp, vp, 128, tid);
    cp_commit();                    // G2
    cp_wait<2>();                   // G0 done
    __syncthreads();

    uint32_t aq[2][2][4];
#pragma unroll
    for (int mt = 0; mt < 2; ++mt)
#pragma unroll
        for (int ks = 0; ks < 2; ++ks) {
            int row = wr * 32 + mt * 16 + (l & 15);
            int cb  = ks * 32 + ((l & 16) ? 16 : 0);
            ldsm_x4(aq[mt][ks], smem_u32(sQ + row * 64 + (cb ^ (((row >> 1) & 3) << 4))));
        }

    float o[2][8][4];
#pragma unroll
    for (int mt = 0; mt < 2; ++mt)
#pragma unroll
        for (int nt = 0; nt < 8; ++nt) { o[mt][nt][0]=0.f; o[mt][nt][1]=0.f; o[mt][nt][2]=0.f; o[mt][nt][3]=0.f; }
    float li[2][2] = {{0.f, 0.f}, {0.f, 0.f}};

    // QK(0) into P buf0
    qk_store(smem, 0, smem + SP_OFF, aq, li, wr, wkc, l);

#pragma unroll 1
    for (int it = 0; it < 64; ++it) {
        __syncthreads();   // P(it) visible; all readers of recycled buffers done

        if (it + 3 < 64) load_kv(smem, (it + 3) & 3, kp, vp, (it + 3) * 64, tid);
        cp_commit();

        char* cV  = smem + SV_OFF + (it & 3) * 16384;
        char* sPc = smem + SP_OFF + (it & 1) * 8192;

        // ---- PV(it): fp8 m16n8k32, ldmatrix frags ----
        uint32_t pA[2][2][4];   // [mt][kchunk]
#pragma unroll
        for (int mt = 0; mt < 2; ++mt)
#pragma unroll
            for (int kc = 0; kc < 2; ++kc) {
                int row = wr * 32 + mt * 16 + (l & 15);
                int cb  = kc * 32 + ((l & 16) ? 16 : 0);
                ldsm_x4(pA[mt][kc], smem_u32(sPc + row * 64 + (cb ^ (((row >> 1) & 3) << 4))));
            }
#pragma unroll
        for (int cg = 0; cg < 4; ++cg) {      // 16 channels per group
#pragma unroll
            for (int kc = 0; kc < 2; ++kc) {  // 32 keys per mma
                uint32_t bv[4];
                int chr = wkc * 64 + cg * 16 + (l & 7) + ((l & 16) ? 8 : 0);
                int cb  = kc * 32 + ((l & 8) ? 16 : 0);
                ldsm_x4(bv, smem_u32(cV + chr * 64 + (cb ^ (((chr >> 1) & 3) << 4))));
#pragma unroll
                for (int mt = 0; mt < 2; ++mt) {
                    mma_fp8(o[mt][cg * 2],     pA[mt][kc], bv);
                    mma_fp8(o[mt][cg * 2 + 1], pA[mt][kc], bv + 2);
                }
            }
        }

        cp_wait<1>();      // stage(it+1) and older guaranteed resident
        if (it + 1 < 64)
            qk_store(smem, (it + 1) & 3, smem + SP_OFF + ((it + 1) & 1) * 8192,
                     aq, li, wr, wkc, l);
    }

    // ---- epilogue: cross-warp row-sum reduction ----
#pragma unroll
    for (int mt = 0; mt < 2; ++mt)
#pragma unroll
        for (int h = 0; h < 2; ++h) {
            li[mt][h] += __shfl_xor_sync(0xffffffffu, li[mt][h], 1);
            li[mt][h] += __shfl_xor_sync(0xffffffffu, li[mt][h], 2);
        }
    if ((l & 3) == 0) {
#pragma unroll
        for (int mt = 0; mt < 2; ++mt)
#pragma unroll
            for (int h = 0; h < 2; ++h)
                sSum[(wr * 32 + mt * 16 + h * 8 + (l >> 2)) * 4 + wkc] = li[mt][h];
    }
    __syncthreads();

#pragma unroll
    for (int mt = 0; mt < 2; ++mt) {
        int r0 = wr * 32 + mt * 16 + (l >> 2);
        float4 s0 = *(float4*)(sSum + r0 * 4);
        float4 s1 = *(float4*)(sSum + (r0 + 8) * 4);
        float i0 = 1.f / (s0.x + s0.y + s0.z + s0.w);
        float i1 = 1.f / (s1.x + s1.y + s1.z + s1.w);
        int tok = m0 + r0;
#pragma unroll
        for (int nt = 0; nt < 8; ++nt) {
            int ch = wkc * 64 + nt * 8 + 2 * (l & 3);
            size_t base0 = ((size_t)(b * CCH + ch)) * NTOK + tok;
            size_t base1 = base0 + NTOK;
            out[base0]     = zin[base0]     + o[mt][nt][0] * i0;
            out[base1]     = zin[base1]     + o[mt][nt][1] * i0;
            out[base0 + 8] = zin[base0 + 8] + o[mt][nt][2] * i1;
            out[base1 + 8] = zin[base1 + 8] + o[mt][nt][3] * i1;
        }
    }
}

extern "C" void kernel_launch(void* const* d_in, const int* in_sizes, int n_in,
                              void* d_out, int out_size) {
    const float* z  = (const float*)d_in[0];
    const float* x  = (const float*)d_in[1];
    const float* y  = (const float*)d_in[2];
    const float* Wq = (const float*)d_in[3];
    const float* bq = (const float*)d_in[4];
    const float* Wk = (const float*)d_in[5];
    const float* bk = (const float*)d_in[6];
    const float* Wv = (const float*)d_in[7];
    const float* bv = (const float*)d_in[8];
    float* out = (float*)d_out;

    cudaFuncSetAttribute(proj_kernel, cudaFuncAttributeMaxDynamicSharedMemorySize,
                         PROJ_SMEM);
    cudaFuncSetAttribute(flash_kernel, cudaFuncAttributeMaxDynamicSharedMemorySize,
                         FLASH_SMEM);

    proj_kernel<<<dim3(64, 4, 3), 256, PROJ_SMEM>>>(z, x, y, Wq, bq, Wk, bk, Wv, bv);
    flash_kernel<<<dim3(32, 4), 512, FLASH_SMEM>>>(z, out);
}

// round 12
// speedup vs baseline: 1.3435x; 1.2156x over previous
#include <cuda_runtime.h>
#include <cuda_bf16.h>
#include <cstdint>

#define BATCH 4
#define CCH   256
#define DQK   32
#define NTOK  4096

__device__ __nv_bfloat16 g_q[BATCH * NTOK * DQK];
__device__ __nv_bfloat16 g_k[BATCH * NTOK * DQK];
__device__ __nv_bfloat16 g_v[BATCH * NTOK * CCH];   // token-major [B,N,C]

__device__ __forceinline__ uint32_t smem_u32(const void* p) {
    return (uint32_t)__cvta_generic_to_shared(p);
}
__device__ __forceinline__ void cp16(uint32_t dst, const void* src) {
    asm volatile("cp.async.cg.shared.global [%0], [%1], 16;\n" :: "r"(dst), "l"(src));
}
__device__ __forceinline__ void cp_commit() { asm volatile("cp.async.commit_group;\n"); }
template <int N> __device__ __forceinline__ void cp_wait() {
    asm volatile("cp.async.wait_group %0;\n" :: "n"(N));
}
__device__ __forceinline__ void ldsm_x4(uint32_t* r, uint32_t a) {
    asm volatile("ldmatrix.sync.aligned.m8n8.x4.shared.b16 {%0,%1,%2,%3}, [%4];\n"
                 : "=r"(r[0]), "=r"(r[1]), "=r"(r[2]), "=r"(r[3]) : "r"(a));
}
__device__ __forceinline__ void ldsm_x4_t(uint32_t* r, uint32_t a) {
    asm volatile("ldmatrix.sync.aligned.m8n8.x4.trans.shared.b16 {%0,%1,%2,%3}, [%4];\n"
                 : "=r"(r[0]), "=r"(r[1]), "=r"(r[2]), "=r"(r[3]) : "r"(a));
}
__device__ __forceinline__ void mma_bf16(float* c, const uint32_t* a, const uint32_t* b) {
    asm volatile(
        "mma.sync.aligned.m16n8k16.row.col.f32.bf16.bf16.f32 "
        "{%0,%1,%2,%3}, {%4,%5,%6,%7}, {%8,%9}, {%0,%1,%2,%3};\n"
        : "+f"(c[0]), "+f"(c[1]), "+f"(c[2]), "+f"(c[3])
        : "r"(a[0]), "r"(a[1]), "r"(a[2]), "r"(a[3]), "r"(b[0]), "r"(b[1]));
}
__device__ __forceinline__ uint32_t packbf(float a, float b) {
    __nv_bfloat162 h = __floats2bfloat162_rn(a, b);
    return reinterpret_cast<uint32_t&>(h);
}
__device__ __forceinline__ float ex2f(float x) {
    float y; asm("ex2.approx.ftz.f32 %0, %1;" : "=f"(y) : "f"(x)); return y;
}

// ===================== projection kernel =====================
#define PROJ_SMEM (32768 + 16384)

__global__ void __launch_bounds__(256, 2)
proj_kernel(const float* __restrict__ zin, const float* __restrict__ xin,
            const float* __restrict__ yin,
            const float* __restrict__ Wq, const float* __restrict__ bq,
            const float* __restrict__ Wk, const float* __restrict__ bk,
            const float* __restrict__ Wv, const float* __restrict__ bv) {
    extern __shared__ char smem[];
    char* sA = smem;            // [c=256][128B] bf16 swizzled
    char* sW = smem + 32768;    // [d=32][512B]  bf16 swizzled

    const int sel = blockIdx.z, b = blockIdx.y, n0 = blockIdx.x * 64;
    const int tid = threadIdx.x, l = tid & 31, wid = tid >> 5;
    const int wr = wid >> 1, wc = wid & 1;

    const float* src  = (sel == 0) ? xin : ((sel == 1) ? yin : zin);
    const float* W    = (sel == 0) ? Wq  : ((sel == 1) ? Wk  : Wv);
    const float* bias = (sel == 0) ? bq  : ((sel == 1) ? bk  : bv);
    __nv_bfloat16* dst = (sel == 0) ? g_q : ((sel == 1) ? g_k : g_v);
    const int dstw    = (sel == 2) ? CCH : DQK;
    const int nchunks = (sel == 2) ? 8 : 1;
    const float osc   = (sel == 0) ? 1.44269504f : 1.0f;   // fold log2(e) into q

#pragma unroll
    for (int j = 0; j < 16; ++j) {
        int id = j * 256 + tid;
        int c = id >> 4, nq = id & 15;
        float4 f = *(const float4*)(src + ((size_t)(b * CCH + c) * NTOK + n0 + nq * 4));
        int nb = nq * 8;
        int phys = c * 128 + ((((nb & ~15) ^ ((c & 7) << 4))) | (nb & 15));
        *(__nv_bfloat162*)(sA + phys)     = __floats2bfloat162_rn(f.x, f.y);
        *(__nv_bfloat162*)(sA + phys + 4) = __floats2bfloat162_rn(f.z, f.w);
    }

    for (int oc = 0; oc < nchunks; ++oc) {
        __syncthreads();
#pragma unroll
        for (int j = 0; j < 8; ++j) {
            int id = j * 256 + tid;
            int dd = id >> 6, cq = id & 63;
            float4 f = *(const float4*)(W + (size_t)(oc * 32 + dd) * CCH + cq * 4);
            int cb = cq * 8;
            int phys = dd * 512 + ((((cb & ~15) ^ ((dd & 7) << 4))) | (cb & 15));
            *(__nv_bfloat162*)(sW + phys)     = __floats2bfloat162_rn(f.x, f.y);
            *(__nv_bfloat162*)(sW + phys + 4) = __floats2bfloat162_rn(f.z, f.w);
        }
        __syncthreads();

        float acc[2][4] = {{0.f,0.f,0.f,0.f},{0.f,0.f,0.f,0.f}};
#pragma unroll
        for (int ks = 0; ks < 16; ++ks) {
            uint32_t aA[4], bw[4];
            int crow = ks * 16 + (l & 7) + ((l & 16) ? 8 : 0);
            int nb   = wr * 32 + ((l & 8) ? 16 : 0);
            ldsm_x4_t(aA, smem_u32(sA + crow * 128 + (nb ^ ((crow & 7) << 4))));
            int dd = wc * 16 + (l & 7) + ((l & 16) ? 8 : 0);
            int cb = ks * 32 + ((l & 8) ? 16 : 0);
            ldsm_x4(bw, smem_u32(sW + dd * 512 + (cb ^ ((dd & 7) << 4))));
            mma_bf16(acc[0], aA, bw);
            mma_bf16(acc[1], aA, bw + 2);
        }

        int nloc = wr * 16 + (l >> 2);
        int dloc = wc * 16 + 2 * (l & 3);
#pragma unroll
        for (int t = 0; t < 2; ++t) {
            int d = oc * 32 + dloc + t * 8;
            float b0 = bias[d], b1 = bias[d + 1];
            *(__nv_bfloat162*)(dst + ((size_t)(b * NTOK + n0 + nloc) * dstw + d)) =
                __floats2bfloat162_rn((acc[t][0] + b0) * osc, (acc[t][1] + b1) * osc);
            *(__nv_bfloat162*)(dst + ((size_t)(b * NTOK + n0 + nloc + 8) * dstw + d)) =
                __floats2bfloat162_rn((acc[t][2] + b0) * osc, (acc[t][3] + b1) * osc);
        }
    }
}

// ===================== flash attention kernel =====================
// M=128 tile, 512 thr = 16 warps = 4 rowgroups x 4 key/ch-groups.
// Nk=64 keys/iter, ONE barrier per iter. QK(it+1) overlaps PV(it);
// P (bf16, 128B rows SW128) double-buffered; 3-stage cp.async KV ring.
// smem: Q 8K | K 3x4K | V 3x32K | P 2x16K | sums 2K = 150KB
#define SQ_OFF 0
#define SK_OFF 8192
#define SV_OFF 20480
#define SP_OFF 118784
#define SS_OFF 151552
#define FLASH_SMEM 153600

__device__ __forceinline__ void load_kv(char* smem, int st,
                                        const __nv_bfloat16* kp,
                                        const __nv_bfloat16* vp,
                                        int n0k, int tid) {
    char* sK = smem + SK_OFF + st * 4096;
    char* sV = smem + SV_OFF + st * 32768;
    if (tid < 256) {   // K: 64 rows x 64B
        int n = tid >> 2, cc = tid & 3;
        cp16(smem_u32(sK + n * 64 + ((cc * 16) ^ (((n >> 1) & 3) << 4))),
             kp + (size_t)(n0k + n) * DQK + cc * 8);
    }
#pragma unroll
    for (int j = 0; j < 4; ++j) {   // V: 64 key rows x 512B
        int id = j * 512 + tid;
        int kk = id >> 5, c16 = id & 31;
        cp16(smem_u32(sV + kk * 512 + ((c16 * 16) ^ ((kk & 7) << 4))),
             vp + (size_t)(n0k + kk) * CCH + c16 * 8);
    }
}

// QK 16 keys/warp (2 x 8-key tiles), exp, bf16 P store (SW128 128B rows)
__device__ __forceinline__ void qk_store(char* smem, int stage, char* sPdst,
                                         const uint32_t (&aq)[2][2][4],
                                         float (&li)[2][2],
                                         int wr, int wkc, int l) {
    char* cK = smem + SK_OFF + stage * 4096;
#pragma unroll
    for (int nt = 0; nt < 2; ++nt) {
        uint32_t bk[4];
        int n  = wkc * 16 + nt * 8 + (l & 7);
        int cb = (l >> 3) << 4;
        ldsm_x4(bk, smem_u32(cK + n * 64 + (cb ^ (((n >> 1) & 3) << 4))));
#pragma unroll
        for (int mt = 0; mt < 2; ++mt) {
            float s[4] = {0.f, 0.f, 0.f, 0.f};
            mma_bf16(s, aq[mt][0], bk);
            mma_bf16(s, aq[mt][1], bk + 2);
            s[0] = ex2f(s[0]); s[1] = ex2f(s[1]);
            s[2] = ex2f(s[2]); s[3] = ex2f(s[3]);
            li[mt][0] += s[0] + s[1];
            li[mt][1] += s[2] + s[3];
            int R0 = wr * 32 + mt * 16 + (l >> 2), R1 = R0 + 8;
            int kb = wkc * 32 + nt * 16 + 4 * (l & 3);
            int hi = kb & ~15, lo = kb & 15;
            *(uint32_t*)(sPdst + R0 * 128 + ((hi ^ ((R0 & 7) << 4)) | lo)) =
                packbf(s[0], s[1]);
            *(uint32_t*)(sPdst + R1 * 128 + ((hi ^ ((R1 & 7) << 4)) | lo)) =
                packbf(s[2], s[3]);
        }
    }
}

__global__ void __launch_bounds__(512, 1)
flash_kernel(const float* __restrict__ zin, float* __restrict__ out) {
    extern __shared__ char smem[];
    char*  sQ   = smem + SQ_OFF;
    float* sSum = (float*)(smem + SS_OFF);

    const int b = blockIdx.y, m0 = blockIdx.x * 128;
    const int tid = threadIdx.x, l = tid & 31, wid = tid >> 5;
    const int wr  = wid >> 2;      // 0..3 : 32-query rowgroup
    const int wkc = wid & 3;       // 0..3 : keygroup (QK) / chgroup (PV)

    const __nv_bfloat16* qp = g_q + (size_t)b * NTOK * DQK;
    const __nv_bfloat16* kp = g_k + (size_t)b * NTOK * DQK;
    const __nv_bfloat16* vp = g_v + (size_t)b * NTOK * CCH;

    {   // Q tile: 128 rows x 64B
        int m = tid >> 2, cc = tid & 3;
        cp16(smem_u32(sQ + m * 64 + ((cc * 16) ^ (((m >> 1) & 3) << 4))),
             qp + (size_t)(m0 + m) * DQK + cc * 8);
    }
    load_kv(smem, 0, kp, vp, 0, tid);
    cp_commit();                    // G0: Q + stage0
    load_kv(smem, 1, kp, vp, 64, tid);
    cp_commit();                    // G1: stage1
    cp_wait<1>();                   // G0 done
    __syncthreads();

    uint32_t aq[2][2][4];
#pragma unroll
    for (int mt = 0; mt < 2; ++mt)
#pragma unroll
        for (int ks = 0; ks < 2; ++ks) {
            int row = wr * 32 + mt * 16 + (l & 15);
            int cb  = ks * 32 + ((l & 16) ? 16 : 0);
            ldsm_x4(aq[mt][ks], smem_u32(sQ + row * 64 + (cb ^ (((row >> 1) & 3) << 4))));
        }

    float o[2][8][4];
#pragma unroll
    for (int mt = 0; mt < 2; ++mt)
#pragma unroll
        for (int nt = 0; nt < 8; ++nt) { o[mt][nt][0]=0.f; o[mt][nt][1]=0.f; o[mt][nt][2]=0.f; o[mt][nt][3]=0.f; }
    float li[2][2] = {{0.f, 0.f}, {0.f, 0.f}};

    // QK(0) into P buf0 (stage0 resident)
    qk_store(smem, 0, smem + SP_OFF, aq, li, wr, wkc, l);

#pragma unroll 1
    for (int it = 0; it < 64; ++it) {
        __syncthreads();   // P(it) visible; all readers of recycled buffers done

        if (it + 2 < 64) load_kv(smem, (it + 2) % 3, kp, vp, (it + 2) * 64, tid);
        cp_commit();

        char* cV  = smem + SV_OFF + (it % 3) * 32768;
        char* sPc = smem + SP_OFF + (it & 1) * 16384;

        // ---- PV(it): 32 q-rows x 64 ch per warp, 64 keys ----
#pragma unroll
        for (int j = 0; j < 4; ++j) {     // 16-key chunks
            uint32_t pA[2][4];
#pragma unroll
            for (int mt = 0; mt < 2; ++mt) {
                int row = wr * 32 + mt * 16 + (l & 15);
                int cb  = j * 32 + ((l & 16) ? 16 : 0);
                ldsm_x4(pA[mt], smem_u32(sPc + row * 128 + (cb ^ ((row & 7) << 4))));
            }
#pragma unroll
            for (int ct = 0; ct < 4; ++ct) {
                uint32_t bv[4];
                int rowv  = j * 16 + (l & 15);
                int cbyte = wkc * 128 + ct * 32 + ((l & 16) ? 16 : 0);
                ldsm_x4_t(bv, smem_u32(cV + rowv * 512 + (cbyte ^ ((rowv & 7) << 4))));
#pragma unroll
                for (int mt = 0; mt < 2; ++mt) {
                    mma_bf16(o[mt][ct * 2],     pA[mt], bv);
                    mma_bf16(o[mt][ct * 2 + 1], pA[mt], bv + 2);
                }
            }
        }

        cp_wait<1>();      // stage(it+1) resident before QK reads it
        if (it + 1 < 64)
            qk_store(smem, (it + 1) % 3, smem + SP_OFF + ((it + 1) & 1) * 16384,
                     aq, li, wr, wkc, l);
    }

    // ---- epilogue: cross-warp row-sum reduction ----
#pragma unroll
    for (int mt = 0; mt < 2; ++mt)
#pragma unroll
        for (int h = 0; h < 2; ++h) {
            li[mt][h] += __shfl_xor_sync(0xffffffffu, li[mt][h], 1);
            li[mt][h] += __shfl_xor_sync(0xffffffffu, li[mt][h], 2);
        }
    if ((l & 3) == 0) {
#pragma unroll
        for (int mt = 0; mt < 2; ++mt)
#pragma unroll
            for (int h = 0; h < 2; ++h)
                sSum[(wr * 32 + mt * 16 + h * 8 + (l >> 2)) * 4 + wkc] = li[mt][h];
    }
    __syncthreads();

#pragma unroll
    for (int mt = 0; mt < 2; ++mt) {
        int r0 = wr * 32 + mt * 16 + (l >> 2);
        float4 s0 = *(float4*)(sSum + r0 * 4);
        float4 s1 = *(float4*)(sSum + (r0 + 8) * 4);
        float i0 = 1.f / (s0.x + s0.y + s0.z + s0.w);
        float i1 = 1.f / (s1.x + s1.y + s1.z + s1.w);
        int tok = m0 + r0;
#pragma unroll
        for (int nt = 0; nt < 8; ++nt) {
            int ch = wkc * 64 + nt * 8 + 2 * (l & 3);
            size_t base0 = ((size_t)(b * CCH + ch)) * NTOK + tok;
            size_t base1 = base0 + NTOK;
            out[base0]     = zin[base0]     + o[mt][nt][0] * i0;
            out[base1]     = zin[base1]     + o[mt][nt][1] * i0;
            out[base0 + 8] = zin[base0 + 8] + o[mt][nt][2] * i1;
            out[base1 + 8] = zin[base1 + 8] + o[mt][nt][3] * i1;
        }
    }
}

extern "C" void kernel_launch(void* const* d_in, const int* in_sizes, int n_in,
                              void* d_out, int out_size) {
    const float* z  = (const float*)d_in[0];
    const float* x  = (const float*)d_in[1];
    const float* y  = (const float*)d_in[2];
    const float* Wq = (const float*)d_in[3];
    const float* bq = (const float*)d_in[4];
    const float* Wk = (const float*)d_in[5];
    const float* bk = (const float*)d_in[6];
    const float* Wv = (const float*)d_in[7];
    const float* bv = (const float*)d_in[8];
    float* out = (float*)d_out;

    cudaFuncSetAttribute(proj_kernel, cudaFuncAttributeMaxDynamicSharedMemorySize,
                         PROJ_SMEM);
    cudaFuncSetAttribute(flash_kernel, cudaFuncAttributeMaxDynamicSharedMemorySize,
                         FLASH_SMEM);

    proj_kernel<<<dim3(64, 4, 3), 256, PROJ_SMEM>>>(z, x, y, Wq, bq, Wk, bk, Wv, bv);
    flash_kernel<<<dim3(32, 4), 512, FLASH_SMEM>>>(z, out);
}

// round 13
// speedup vs baseline: 1.3719x; 1.0211x over previous
#include <cuda_runtime.h>
#include <cuda_bf16.h>
#include <cstdint>

#define BATCH 4
#define CCH   256
#define DQK   32
#define NTOK  4096

__device__ __nv_bfloat16 g_q[BATCH * NTOK * DQK];
__device__ __nv_bfloat16 g_k[BATCH * NTOK * DQK];
__device__ __nv_bfloat16 g_v[BATCH * NTOK * CCH];   // token-major [B,N,C]

__device__ __forceinline__ uint32_t smem_u32(const void* p) {
    return (uint32_t)__cvta_generic_to_shared(p);
}
__device__ __forceinline__ void cp16(uint32_t dst, const void* src) {
    asm volatile("cp.async.cg.shared.global [%0], [%1], 16;\n" :: "r"(dst), "l"(src));
}
__device__ __forceinline__ void cp_commit() { asm volatile("cp.async.commit_group;\n"); }
template <int N> __device__ __forceinline__ void cp_wait() {
    asm volatile("cp.async.wait_group %0;\n" :: "n"(N));
}
__device__ __forceinline__ void ldsm_x4(uint32_t* r, uint32_t a) {
    asm volatile("ldmatrix.sync.aligned.m8n8.x4.shared.b16 {%0,%1,%2,%3}, [%4];\n"
                 : "=r"(r[0]), "=r"(r[1]), "=r"(r[2]), "=r"(r[3]) : "r"(a));
}
__device__ __forceinline__ void ldsm_x4_t(uint32_t* r, uint32_t a) {
    asm volatile("ldmatrix.sync.aligned.m8n8.x4.trans.shared.b16 {%0,%1,%2,%3}, [%4];\n"
                 : "=r"(r[0]), "=r"(r[1]), "=r"(r[2]), "=r"(r[3]) : "r"(a));
}
__device__ __forceinline__ void mma_bf16(float* c, const uint32_t* a, const uint32_t* b) {
    asm volatile(
        "mma.sync.aligned.m16n8k16.row.col.f32.bf16.bf16.f32 "
        "{%0,%1,%2,%3}, {%4,%5,%6,%7}, {%8,%9}, {%0,%1,%2,%3};\n"
        : "+f"(c[0]), "+f"(c[1]), "+f"(c[2]), "+f"(c[3])
        : "r"(a[0]), "r"(a[1]), "r"(a[2]), "r"(a[3]), "r"(b[0]), "r"(b[1]));
}
__device__ __forceinline__ uint32_t packbf(float a, float b) {
    __nv_bfloat162 h = __floats2bfloat162_rn(a, b);
    return reinterpret_cast<uint32_t&>(h);
}
__device__ __forceinline__ float ex2f(float x) {
    float y; asm("ex2.approx.ftz.f32 %0, %1;" : "=f"(y) : "f"(x)); return y;
}

// ===================== projection kernel =====================
#define PROJ_SMEM (32768 + 16384)

__global__ void __launch_bounds__(256, 2)
proj_kernel(const float* __restrict__ zin, const float* __restrict__ xin,
            const float* __restrict__ yin,
            const float* __restrict__ Wq, const float* __restrict__ bq,
            const float* __restrict__ Wk, const float* __restrict__ bk,
            const float* __restrict__ Wv, const float* __restrict__ bv) {
    extern __shared__ char smem[];
    char* sA = smem;            // [c=256][128B] bf16 swizzled
    char* sW = smem + 32768;    // [d=32][512B]  bf16 swizzled

    const int sel = blockIdx.z, b = blockIdx.y, n0 = blockIdx.x * 64;
    const int tid = threadIdx.x, l = tid & 31, wid = tid >> 5;
    const int wr = wid >> 1, wc = wid & 1;

    const float* src  = (sel == 0) ? xin : ((sel == 1) ? yin : zin);
    const float* W    = (sel == 0) ? Wq  : ((sel == 1) ? Wk  : Wv);
    const float* bias = (sel == 0) ? bq  : ((sel == 1) ? bk  : bv);
    __nv_bfloat16* dst = (sel == 0) ? g_q : ((sel == 1) ? g_k : g_v);
    const int dstw    = (sel == 2) ? CCH : DQK;
    const int nchunks = (sel == 2) ? 8 : 1;
    const float osc   = (sel == 0) ? 1.44269504f : 1.0f;   // fold log2(e) into q

#pragma unroll
    for (int j = 0; j < 16; ++j) {
        int id = j * 256 + tid;
        int c = id >> 4, nq = id & 15;
        float4 f = *(const float4*)(src + ((size_t)(b * CCH + c) * NTOK + n0 + nq * 4));
        int nb = nq * 8;
        int phys = c * 128 + ((((nb & ~15) ^ ((c & 7) << 4))) | (nb & 15));
        *(__nv_bfloat162*)(sA + phys)     = __floats2bfloat162_rn(f.x, f.y);
        *(__nv_bfloat162*)(sA + phys + 4) = __floats2bfloat162_rn(f.z, f.w);
    }

    for (int oc = 0; oc < nchunks; ++oc) {
        __syncthreads();
#pragma unroll
        for (int j = 0; j < 8; ++j) {
            int id = j * 256 + tid;
            int dd = id >> 6, cq = id & 63;
            float4 f = *(const float4*)(W + (size_t)(oc * 32 + dd) * CCH + cq * 4);
            int cb = cq * 8;
            int phys = dd * 512 + ((((cb & ~15) ^ ((dd & 7) << 4))) | (cb & 15));
            *(__nv_bfloat162*)(sW + phys)     = __floats2bfloat162_rn(f.x, f.y);
            *(__nv_bfloat162*)(sW + phys + 4) = __floats2bfloat162_rn(f.z, f.w);
        }
        __syncthreads();

        float acc[2][4] = {{0.f,0.f,0.f,0.f},{0.f,0.f,0.f,0.f}};
#pragma unroll
        for (int ks = 0; ks < 16; ++ks) {
            uint32_t aA[4], bw[4];
            int crow = ks * 16 + (l & 7) + ((l & 16) ? 8 : 0);
            int nb   = wr * 32 + ((l & 8) ? 16 : 0);
            ldsm_x4_t(aA, smem_u32(sA + crow * 128 + (nb ^ ((crow & 7) << 4))));
            int dd = wc * 16 + (l & 7) + ((l & 16) ? 8 : 0);
            int cb = ks * 32 + ((l & 8) ? 16 : 0);
            ldsm_x4(bw, smem_u32(sW + dd * 512 + (cb ^ ((dd & 7) << 4))));
            mma_bf16(acc[0], aA, bw);
            mma_bf16(acc[1], aA, bw + 2);
        }

        int nloc = wr * 16 + (l >> 2);
        int dloc = wc * 16 + 2 * (l & 3);
#pragma unroll
        for (int t = 0; t < 2; ++t) {
            int d = oc * 32 + dloc + t * 8;
            float b0 = bias[d], b1 = bias[d + 1];
            *(__nv_bfloat162*)(dst + ((size_t)(b * NTOK + n0 + nloc) * dstw + d)) =
                __floats2bfloat162_rn((acc[t][0] + b0) * osc, (acc[t][1] + b1) * osc);
            *(__nv_bfloat162*)(dst + ((size_t)(b * NTOK + n0 + nloc + 8) * dstw + d)) =
                __floats2bfloat162_rn((acc[t][2] + b0) * osc, (acc[t][3] + b1) * osc);
        }
    }
}

// ===================== flash attention kernel =====================
// M=128 tile, 512 thr = 16 warps = 4 rowgroups x 4 key/ch-groups.
// Nk=64 keys/iter, ONE barrier/iter. QK(it+1) instruction stream is
// INTERLEAVED into the PV(it) chunk loop (independent register chains ->
// intra-warp latency hiding). 3-stage cp.async KV ring, P double-buffered.
// smem: Q 8K | K 3x4K | V 3x32K | P 2x16K | sums 2K = 150KB
#define SQ_OFF 0
#define SK_OFF 8192
#define SV_OFF 20480
#define SP_OFF 118784
#define SS_OFF 151552
#define FLASH_SMEM 153600

__device__ __forceinline__ void load_kv(char* smem, int st,
                                        const __nv_bfloat16* kp,
                                        const __nv_bfloat16* vp,
                                        int n0k, int tid) {
    char* sK = smem + SK_OFF + st * 4096;
    char* sV = smem + SV_OFF + st * 32768;
    if (tid < 256) {   // K: 64 rows x 64B
        int n = tid >> 2, cc = tid & 3;
        cp16(smem_u32(sK + n * 64 + ((cc * 16) ^ (((n >> 1) & 3) << 4))),
             kp + (size_t)(n0k + n) * DQK + cc * 8);
    }
#pragma unroll
    for (int j = 0; j < 4; ++j) {   // V: 64 key rows x 512B
        int id = j * 512 + tid;
        int kk = id >> 5, c16 = id & 31;
        cp16(smem_u32(sV + kk * 512 + ((c16 * 16) ^ ((kk & 7) << 4))),
             vp + (size_t)(n0k + kk) * CCH + c16 * 8);
    }
}

// QK(0) prologue version (unfused)
__device__ __forceinline__ void qk_store(char* smem, int stage, char* sPdst,
                                         const uint32_t (&aq)[2][2][4],
                                         float (&li)[2][2],
                                         int wr, int wkc, int l) {
    char* cK = smem + SK_OFF + stage * 4096;
#pragma unroll
    for (int nt = 0; nt < 2; ++nt) {
        uint32_t bk[4];
        int n  = wkc * 16 + nt * 8 + (l & 7);
        int cb = (l >> 3) << 4;
        ldsm_x4(bk, smem_u32(cK + n * 64 + (cb ^ (((n >> 1) & 3) << 4))));
#pragma unroll
        for (int mt = 0; mt < 2; ++mt) {
            float s[4] = {0.f, 0.f, 0.f, 0.f};
            mma_bf16(s, aq[mt][0], bk);
            mma_bf16(s, aq[mt][1], bk + 2);
            s[0] = ex2f(s[0]); s[1] = ex2f(s[1]);
            s[2] = ex2f(s[2]); s[3] = ex2f(s[3]);
            li[mt][0] += s[0] + s[1];
            li[mt][1] += s[2] + s[3];
            int R0 = wr * 32 + mt * 16 + (l >> 2), R1 = R0 + 8;
            int kb = wkc * 32 + nt * 16 + 4 * (l & 3);
            int hi = kb & ~15, lo = kb & 15;
            *(uint32_t*)(sPdst + R0 * 128 + ((hi ^ ((R0 & 7) << 4)) | lo)) =
                packbf(s[0], s[1]);
            *(uint32_t*)(sPdst + R1 * 128 + ((hi ^ ((R1 & 7) << 4)) | lo)) =
                packbf(s[2], s[3]);
        }
    }
}

__global__ void __launch_bounds__(512, 1)
flash_kernel(const float* __restrict__ zin, float* __restrict__ out) {
    extern __shared__ char smem[];
    char*  sQ   = smem + SQ_OFF;
    float* sSum = (float*)(smem + SS_OFF);

    const int b = blockIdx.y, m0 = blockIdx.x * 128;
    const int tid = threadIdx.x, l = tid & 31, wid = tid >> 5;
    const int wr  = wid >> 2;      // 0..3 : 32-query rowgroup
    const int wkc = wid & 3;       // 0..3 : keygroup (QK) / chgroup (PV)

    const __nv_bfloat16* qp = g_q + (size_t)b * NTOK * DQK;
    const __nv_bfloat16* kp = g_k + (size_t)b * NTOK * DQK;
    const __nv_bfloat16* vp = g_v + (size_t)b * NTOK * CCH;

    {   // Q tile: 128 rows x 64B
        int m = tid >> 2, cc = tid & 3;
        cp16(smem_u32(sQ + m * 64 + ((cc * 16) ^ (((m >> 1) & 3) << 4))),
             qp + (size_t)(m0 + m) * DQK + cc * 8);
    }
    load_kv(smem, 0, kp, vp, 0, tid);
    cp_commit();                    // G0: Q + stage0
    load_kv(smem, 1, kp, vp, 64, tid);
    cp_commit();                    // G1: stage1
    cp_wait<1>();                   // G0 done
    __syncthreads();

    uint32_t aq[2][2][4];
#pragma unroll
    for (int mt = 0; mt < 2; ++mt)
#pragma unroll
        for (int ks = 0; ks < 2; ++ks) {
            int row = wr * 32 + mt * 16 + (l & 15);
            int cb  = ks * 32 + ((l & 16) ? 16 : 0);
            ldsm_x4(aq[mt][ks], smem_u32(sQ + row * 64 + (cb ^ (((row >> 1) & 3) << 4))));
        }

    float o[2][8][4];
#pragma unroll
    for (int mt = 0; mt < 2; ++mt)
#pragma unroll
        for (int nt = 0; nt < 8; ++nt) { o[mt][nt][0]=0.f; o[mt][nt][1]=0.f; o[mt][nt][2]=0.f; o[mt][nt][3]=0.f; }
    float li[2][2] = {{0.f, 0.f}, {0.f, 0.f}};

    // QK(0) into P buf0 (stage0 resident)
    qk_store(smem, 0, smem + SP_OFF, aq, li, wr, wkc, l);

    // precomputed per-thread QK/P constants
    const int qkR0base = wr * 32 + (l >> 2);          // + mt*16 (+8)
    const int qkKbase  = wkc * 32 + 4 * (l & 3);      // + nt*16
    const int qkNbase  = wkc * 16 + (l & 7);          // + nt*8
    const int qkCb     = (l >> 3) << 4;

#pragma unroll 1
    for (int it = 0; it < 64; ++it) {
        __syncthreads();   // P(it) visible; all readers of recycled buffers done

        if (it + 2 < 64) load_kv(smem, (it + 2) % 3, kp, vp, (it + 2) * 64, tid);
        cp_commit();
        cp_wait<1>();      // stage(it+1) resident (issued 2 iters ago)

        char* cV  = smem + SV_OFF + (it % 3) * 32768;
        char* sPc = smem + SP_OFF + (it & 1) * 16384;
        char* cK1 = smem + SK_OFF + ((it + 1) % 3) * 4096;
        char* sPn = smem + SP_OFF + ((it + 1) & 1) * 16384;
        const bool doqk = (it + 1 < 64);

        uint32_t bk[4];
        // ---- fused loop: PV(it) chunk j  +  QK(it+1) piece j ----
#pragma unroll
        for (int j = 0; j < 4; ++j) {
            // -- PV chunk j: 16 keys, 32 rows x 64 ch --
            uint32_t pA[2][4];
#pragma unroll
            for (int mt = 0; mt < 2; ++mt) {
                int row = wr * 32 + mt * 16 + (l & 15);
                int cb  = j * 32 + ((l & 16) ? 16 : 0);
                ldsm_x4(pA[mt], smem_u32(sPc + row * 128 + (cb ^ ((row & 7) << 4))));
            }
            uint32_t bv[4];
            {
                int rowv  = j * 16 + (l & 15);
                int cbyte = wkc * 128 + ((l & 16) ? 16 : 0);
                ldsm_x4_t(bv, smem_u32(cV + rowv * 512 + (cbyte ^ ((rowv & 7) << 4))));
            }
#pragma unroll
            for (int ct = 0; ct < 4; ++ct) {
                uint32_t bvn[4];
                if (ct < 3) {   // prefetch next channel group's V frag
                    int rowv  = j * 16 + (l & 15);
                    int cbyte = wkc * 128 + (ct + 1) * 32 + ((l & 16) ? 16 : 0);
                    ldsm_x4_t(bvn, smem_u32(cV + rowv * 512 + (cbyte ^ ((rowv & 7) << 4))));
                }
#pragma unroll
                for (int mt = 0; mt < 2; ++mt) {
                    mma_bf16(o[mt][ct * 2],     pA[mt], bv);
                    mma_bf16(o[mt][ct * 2 + 1], pA[mt], bv + 2);
                }
                if (ct < 3) { bv[0]=bvn[0]; bv[1]=bvn[1]; bv[2]=bvn[2]; bv[3]=bvn[3]; }
            }

            // -- QK piece j: nt = j>>1, mt = j&1 --
            if (doqk) {
                const int nt = j >> 1, mt = j & 1;
                if ((j & 1) == 0) {
                    int n = qkNbase + nt * 8;
                    ldsm_x4(bk, smem_u32(cK1 + n * 64 + (qkCb ^ (((n >> 1) & 3) << 4))));
                }
                float s[4] = {0.f, 0.f, 0.f, 0.f};
                mma_bf16(s, aq[mt][0], bk);
                mma_bf16(s, aq[mt][1], bk + 2);
                s[0] = ex2f(s[0]); s[1] = ex2f(s[1]);
                s[2] = ex2f(s[2]); s[3] = ex2f(s[3]);
                li[mt][0] += s[0] + s[1];
                li[mt][1] += s[2] + s[3];
                int R0 = qkR0base + mt * 16, R1 = R0 + 8;
                int kb = qkKbase + nt * 16;
                int hi = kb & ~15, lo = kb & 15;
                *(uint32_t*)(sPn + R0 * 128 + ((hi ^ ((R0 & 7) << 4)) | lo)) =
                    packbf(s[0], s[1]);
                *(uint32_t*)(sPn + R1 * 128 + ((hi ^ ((R1 & 7) << 4)) | lo)) =
                    packbf(s[2], s[3]);
            }
        }
    }

    // ---- epilogue: cross-warp row-sum reduction ----
#pragma unroll
    for (int mt = 0; mt < 2; ++mt)
#pragma unroll
        for (int h = 0; h < 2; ++h) {
            li[mt][h] += __shfl_xor_sync(0xffffffffu, li[mt][h], 1);
            li[mt][h] += __shfl_xor_sync(0xffffffffu, li[mt][h], 2);
        }
    if ((l & 3) == 0) {
#pragma unroll
        for (int mt = 0; mt < 2; ++mt)
#pragma unroll
            for (int h = 0; h < 2; ++h)
                sSum[(wr * 32 + mt * 16 + h * 8 + (l >> 2)) * 4 + wkc] = li[mt][h];
    }
    __syncthreads();

#pragma unroll
    for (int mt = 0; mt < 2; ++mt) {
        int r0 = wr * 32 + mt * 16 + (l >> 2);
        float4 s0 = *(float4*)(sSum + r0 * 4);
        float4 s1 = *(float4*)(sSum + (r0 + 8) * 4);
        float i0 = 1.f / (s0.x + s0.y + s0.z + s0.w);
        float i1 = 1.f / (s1.x + s1.y + s1.z + s1.w);
        int tok = m0 + r0;
#pragma unroll
        for (int nt = 0; nt < 8; ++nt) {
            int ch = wkc * 64 + nt * 8 + 2 * (l & 3);
            size_t base0 = ((size_t)(b * CCH + ch)) * NTOK + tok;
            size_t base1 = base0 + NTOK;
            out[base0]     = zin[base0]     + o[mt][nt][0] * i0;
            out[base1]     = zin[base1]     + o[mt][nt][1] * i0;
            out[base0 + 8] = zin[base0 + 8] + o[mt][nt][2] * i1;
            out[base1 + 8] = zin[base1 + 8] + o[mt][nt][3] * i1;
        }
    }
}

extern "C" void kernel_launch(void* const* d_in, const int* in_sizes, int n_in,
                              void* d_out, int out_size) {
    const float* z  = (const float*)d_in[0];
    const float* x  = (const float*)d_in[1];
    const float* y  = (const float*)d_in[2];
    const float* Wq = (const float*)d_in[3];
    const float* bq = (const float*)d_in[4];
    const float* Wk = (const float*)d_in[5];
    const float* bk = (const float*)d_in[6];
    const float* Wv = (const float*)d_in[7];
    const float* bv = (const float*)d_in[8];
    float* out = (float*)d_out;

    cudaFuncSetAttribute(proj_kernel, cudaFuncAttributeMaxDynamicSharedMemorySize,
                         PROJ_SMEM);
    cudaFuncSetAttribute(flash_kernel, cudaFuncAttributeMaxDynamicSharedMemorySize,
                         FLASH_SMEM);

    proj_kernel<<<dim3(64, 4, 3), 256, PROJ_SMEM>>>(z, x, y, Wq, bq, Wk, bk, Wv, bv);
    flash_kernel<<<dim3(32, 4), 512, FLASH_SMEM>>>(z, out);
}

// round 14
// speedup vs baseline: 1.3786x; 1.0049x over previous
#include <cuda_runtime.h>
#include <cuda_bf16.h>
#include <cstdint>

#define BATCH 4
#define CCH   256
#define DQK   32
#define NTOK  4096

__device__ __nv_bfloat16 g_q[BATCH * NTOK * DQK];
__device__ __nv_bfloat16 g_k[BATCH * NTOK * DQK];
__device__ __nv_bfloat16 g_v[BATCH * NTOK * CCH];   // token-major [B,N,C]

__device__ __forceinline__ uint32_t smem_u32(const void* p) {
    return (uint32_t)__cvta_generic_to_shared(p);
}
__device__ __forceinline__ void cp16(uint32_t dst, const void* src) {
    asm volatile("cp.async.cg.shared.global [%0], [%1], 16;\n" :: "r"(dst), "l"(src));
}
__device__ __forceinline__ void cp_commit() { asm volatile("cp.async.commit_group;\n"); }
template <int N> __device__ __forceinline__ void cp_wait() {
    asm volatile("cp.async.wait_group %0;\n" :: "n"(N));
}
__device__ __forceinline__ void ldsm_x4(uint32_t* r, uint32_t a) {
    asm volatile("ldmatrix.sync.aligned.m8n8.x4.shared.b16 {%0,%1,%2,%3}, [%4];\n"
                 : "=r"(r[0]), "=r"(r[1]), "=r"(r[2]), "=r"(r[3]) : "r"(a));
}
__device__ __forceinline__ void ldsm_x4_t(uint32_t* r, uint32_t a) {
    asm volatile("ldmatrix.sync.aligned.m8n8.x4.trans.shared.b16 {%0,%1,%2,%3}, [%4];\n"
                 : "=r"(r[0]), "=r"(r[1]), "=r"(r[2]), "=r"(r[3]) : "r"(a));
}
__device__ __forceinline__ void mma_bf16(float* c, const uint32_t* a, const uint32_t* b) {
    asm volatile(
        "mma.sync.aligned.m16n8k16.row.col.f32.bf16.bf16.f32 "
        "{%0,%1,%2,%3}, {%4,%5,%6,%7}, {%8,%9}, {%0,%1,%2,%3};\n"
        : "+f"(c[0]), "+f"(c[1]), "+f"(c[2]), "+f"(c[3])
        : "r"(a[0]), "r"(a[1]), "r"(a[2]), "r"(a[3]), "r"(b[0]), "r"(b[1]));
}
__device__ __forceinline__ uint32_t packbf(float a, float b) {
    __nv_bfloat162 h = __floats2bfloat162_rn(a, b);
    return reinterpret_cast<uint32_t&>(h);
}
__device__ __forceinline__ float ex2f(float x) {
    float y; asm("ex2.approx.ftz.f32 %0, %1;" : "=f"(y) : "f"(x)); return y;
}

// ===================== projection kernel =====================
// sA 32KB | sW 2x16KB double buffer = 64KB. W chunk register-prefetched:
// one barrier per chunk, LDG latency hidden under MMA compute.
#define PROJ_SMEM (32768 + 32768)

__global__ void __launch_bounds__(256, 2)
proj_kernel(const float* __restrict__ zin, const float* __restrict__ xin,
            const float* __restrict__ yin,
            const float* __restrict__ Wq, const float* __restrict__ bq,
            const float* __restrict__ Wk, const float* __restrict__ bk,
            const float* __restrict__ Wv, const float* __restrict__ bv) {
    extern __shared__ char smem[];
    char* sA = smem;            // [c=256][128B] bf16 swizzled
    char* sW = smem + 32768;    // 2 x [d=32][512B] bf16 swizzled

    const int sel = blockIdx.z, b = blockIdx.y, n0 = blockIdx.x * 64;
    const int tid = threadIdx.x, l = tid & 31, wid = tid >> 5;
    const int wr = wid >> 1, wc = wid & 1;

    const float* src  = (sel == 0) ? xin : ((sel == 1) ? yin : zin);
    const float* W    = (sel == 0) ? Wq  : ((sel == 1) ? Wk  : Wv);
    const float* bias = (sel == 0) ? bq  : ((sel == 1) ? bk  : bv);
    __nv_bfloat16* dst = (sel == 0) ? g_q : ((sel == 1) ? g_k : g_v);
    const int dstw    = (sel == 2) ? CCH : DQK;
    const int nchunks = (sel == 2) ? 8 : 1;
    const float osc   = (sel == 0) ? 1.44269504f : 1.0f;   // fold log2(e) into q

    // per-thread W-load indices (32 floats per thread per chunk)
    const int wdd[2] = { tid >> 6, 4 + (tid >> 6) };       // j<4 / j>=4 row pairs? no:
    // id = j*256 + tid ; dd = id>>6 = j*4 + (tid>>6) ; cq = id&63 = tid&63
    const int wcq = tid & 63;

    // prologue: W chunk 0 into registers
    float4 wreg[8];
#pragma unroll
    for (int j = 0; j < 8; ++j)
        wreg[j] = *(const float4*)(W + (size_t)(j * 4 + (tid >> 6)) * CCH + wcq * 4);

    // A tile: [256 c][64 n] fp32 -> bf16 smem (swizzled)
#pragma unroll
    for (int j = 0; j < 16; ++j) {
        int id = j * 256 + tid;
        int c = id >> 4, nq = id & 15;
        float4 f = *(const float4*)(src + ((size_t)(b * CCH + c) * NTOK + n0 + nq * 4));
        int nb = nq * 8;
        int phys = c * 128 + ((((nb & ~15) ^ ((c & 7) << 4))) | (nb & 15));
        *(__nv_bfloat162*)(sA + phys)     = __floats2bfloat162_rn(f.x, f.y);
        *(__nv_bfloat162*)(sA + phys + 4) = __floats2bfloat162_rn(f.z, f.w);
    }

    for (int oc = 0; oc < nchunks; ++oc) {
        char* sWc = sW + (oc & 1) * 16384;
        // convert regs -> sW half (writes to half not being read by stragglers)
#pragma unroll
        for (int j = 0; j < 8; ++j) {
            int dd = j * 4 + (tid >> 6);
            int cb = wcq * 8;
            int phys = dd * 512 + ((((cb & ~15) ^ ((dd & 7) << 4))) | (cb & 15));
            *(__nv_bfloat162*)(sWc + phys)     = __floats2bfloat162_rn(wreg[j].x, wreg[j].y);
            *(__nv_bfloat162*)(sWc + phys + 4) = __floats2bfloat162_rn(wreg[j].z, wreg[j].w);
        }
        // prefetch next W chunk (latency hidden under compute below)
        if (oc + 1 < nchunks) {
#pragma unroll
            for (int j = 0; j < 8; ++j)
                wreg[j] = *(const float4*)(W + (size_t)((oc + 1) * 32 + j * 4 + (tid >> 6)) * CCH + wcq * 4);
        }
        __syncthreads();   // sA (first iter) + sWc ready; prior compute done

        float acc[2][4] = {{0.f,0.f,0.f,0.f},{0.f,0.f,0.f,0.f}};
#pragma unroll
        for (int ks = 0; ks < 16; ++ks) {
            uint32_t aA[4], bw[4];
            int crow = ks * 16 + (l & 7) + ((l & 16) ? 8 : 0);
            int nb   = wr * 32 + ((l & 8) ? 16 : 0);
            ldsm_x4_t(aA, smem_u32(sA + crow * 128 + (nb ^ ((crow & 7) << 4))));
            int dd = wc * 16 + (l & 7) + ((l & 16) ? 8 : 0);
            int cb = ks * 32 + ((l & 8) ? 16 : 0);
            ldsm_x4(bw, smem_u32(sWc + dd * 512 + (cb ^ ((dd & 7) << 4))));
            mma_bf16(acc[0], aA, bw);
            mma_bf16(acc[1], aA, bw + 2);
        }

        int nloc = wr * 16 + (l >> 2);
        int dloc = wc * 16 + 2 * (l & 3);
#pragma unroll
        for (int t = 0; t < 2; ++t) {
            int d = oc * 32 + dloc + t * 8;
            float b0 = bias[d], b1 = bias[d + 1];
            *(__nv_bfloat162*)(dst + ((size_t)(b * NTOK + n0 + nloc) * dstw + d)) =
                __floats2bfloat162_rn((acc[t][0] + b0) * osc, (acc[t][1] + b1) * osc);
            *(__nv_bfloat162*)(dst + ((size_t)(b * NTOK + n0 + nloc + 8) * dstw + d)) =
                __floats2bfloat162_rn((acc[t][2] + b0) * osc, (acc[t][3] + b1) * osc);
        }
    }
}

// ===================== flash attention kernel (R12 best: 120.9us) =====================
#define SQ_OFF 0
#define SK_OFF 8192
#define SV_OFF 20480
#define SP_OFF 118784
#define SS_OFF 151552
#define FLASH_SMEM 153600

__device__ __forceinline__ void load_kv(char* smem, int st,
                                        const __nv_bfloat16* kp,
                                        const __nv_bfloat16* vp,
                                        int n0k, int tid) {
    char* sK = smem + SK_OFF + st * 4096;
    char* sV = smem + SV_OFF + st * 32768;
    if (tid < 256) {   // K: 64 rows x 64B
        int n = tid >> 2, cc = tid & 3;
        cp16(smem_u32(sK + n * 64 + ((cc * 16) ^ (((n >> 1) & 3) << 4))),
             kp + (size_t)(n0k + n) * DQK + cc * 8);
    }
#pragma unroll
    for (int j = 0; j < 4; ++j) {   // V: 64 key rows x 512B
        int id = j * 512 + tid;
        int kk = id >> 5, c16 = id & 31;
        cp16(smem_u32(sV + kk * 512 + ((c16 * 16) ^ ((kk & 7) << 4))),
             vp + (size_t)(n0k + kk) * CCH + c16 * 8);
    }
}

__device__ __forceinline__ void qk_store(char* smem, int stage, char* sPdst,
                                         const uint32_t (&aq)[2][2][4],
                                         float (&li)[2][2],
                                         int wr, int wkc, int l) {
    char* cK = smem + SK_OFF + stage * 4096;
#pragma unroll
    for (int nt = 0; nt < 2; ++nt) {
        uint32_t bk[4];
        int n  = wkc * 16 + nt * 8 + (l & 7);
        int cb = (l >> 3) << 4;
        ldsm_x4(bk, smem_u32(cK + n * 64 + (cb ^ (((n >> 1) & 3) << 4))));
#pragma unroll
        for (int mt = 0; mt < 2; ++mt) {
            float s[4] = {0.f, 0.f, 0.f, 0.f};
            mma_bf16(s, aq[mt][0], bk);
            mma_bf16(s, aq[mt][1], bk + 2);
            s[0] = ex2f(s[0]); s[1] = ex2f(s[1]);
            s[2] = ex2f(s[2]); s[3] = ex2f(s[3]);
            li[mt][0] += s[0] + s[1];
            li[mt][1] += s[2] + s[3];
            int R0 = wr * 32 + mt * 16 + (l >> 2), R1 = R0 + 8;
            int kb = wkc * 32 + nt * 16 + 4 * (l & 3);
            int hi = kb & ~15, lo = kb & 15;
            *(uint32_t*)(sPdst + R0 * 128 + ((hi ^ ((R0 & 7) << 4)) | lo)) =
                packbf(s[0], s[1]);
            *(uint32_t*)(sPdst + R1 * 128 + ((hi ^ ((R1 & 7) << 4)) | lo)) =
                packbf(s[2], s[3]);
        }
    }
}

__global__ void __launch_bounds__(512, 1)
flash_kernel(const float* __restrict__ zin, float* __restrict__ out) {
    extern __shared__ char smem[];
    char*  sQ   = smem + SQ_OFF;
    float* sSum = (float*)(smem + SS_OFF);

    const int b = blockIdx.y, m0 = blockIdx.x * 128;
    const int tid = threadIdx.x, l = tid & 31, wid = tid >> 5;
    const int wr  = wid >> 2;
    const int wkc = wid & 3;

    const __nv_bfloat16* qp = g_q + (size_t)b * NTOK * DQK;
    const __nv_bfloat16* kp = g_k + (size_t)b * NTOK * DQK;
    const __nv_bfloat16* vp = g_v + (size_t)b * NTOK * CCH;

    {
        int m = tid >> 2, cc = tid & 3;
        cp16(smem_u32(sQ + m * 64 + ((cc * 16) ^ (((m >> 1) & 3) << 4))),
             qp + (size_t)(m0 + m) * DQK + cc * 8);
    }
    load_kv(smem, 0, kp, vp, 0, tid);
    cp_commit();
    load_kv(smem, 1, kp, vp, 64, tid);
    cp_commit();
    cp_wait<1>();
    __syncthreads();

    uint32_t aq[2][2][4];
#pragma unroll
    for (int mt = 0; mt < 2; ++mt)
#pragma unroll
        for (int ks = 0; ks < 2; ++ks) {
            int row = wr * 32 + mt * 16 + (l & 15);
            int cb  = ks * 32 + ((l & 16) ? 16 : 0);
            ldsm_x4(aq[mt][ks], smem_u32(sQ + row * 64 + (cb ^ (((row >> 1) & 3) << 4))));
        }

    float o[2][8][4];
#pragma unroll
    for (int mt = 0; mt < 2; ++mt)
#pragma unroll
        for (int nt = 0; nt < 8; ++nt) { o[mt][nt][0]=0.f; o[mt][nt][1]=0.f; o[mt][nt][2]=0.f; o[mt][nt][3]=0.f; }
    float li[2][2] = {{0.f, 0.f}, {0.f, 0.f}};

    qk_store(smem, 0, smem + SP_OFF, aq, li, wr, wkc, l);

    const int qkR0base = wr * 32 + (l >> 2);
    const int qkKbase  = wkc * 32 + 4 * (l & 3);
    const int qkNbase  = wkc * 16 + (l & 7);
    const int qkCb     = (l >> 3) << 4;

#pragma unroll 1
    for (int it = 0; it < 64; ++it) {
        __syncthreads();

        if (it + 2 < 64) load_kv(smem, (it + 2) % 3, kp, vp, (it + 2) * 64, tid);
        cp_commit();
        cp_wait<1>();

        char* cV  = smem + SV_OFF + (it % 3) * 32768;
        char* sPc = smem + SP_OFF + (it & 1) * 16384;
        char* cK1 = smem + SK_OFF + ((it + 1) % 3) * 4096;
        char* sPn = smem + SP_OFF + ((it + 1) & 1) * 16384;
        const bool doqk = (it + 1 < 64);

        uint32_t bk[4];
#pragma unroll
        for (int j = 0; j < 4; ++j) {
            uint32_t pA[2][4];
#pragma unroll
            for (int mt = 0; mt < 2; ++mt) {
                int row = wr * 32 + mt * 16 + (l & 15);
                int cb  = j * 32 + ((l & 16) ? 16 : 0);
                ldsm_x4(pA[mt], smem_u32(sPc + row * 128 + (cb ^ ((row & 7) << 4))));
            }
            uint32_t bv[4];
            {
                int rowv  = j * 16 + (l & 15);
                int cbyte = wkc * 128 + ((l & 16) ? 16 : 0);
                ldsm_x4_t(bv, smem_u32(cV + rowv * 512 + (cbyte ^ ((rowv & 7) << 4))));
            }
#pragma unroll
            for (int ct = 0; ct < 4; ++ct) {
                uint32_t bvn[4];
                if (ct < 3) {
                    int rowv  = j * 16 + (l & 15);
                    int cbyte = wkc * 128 + (ct + 1) * 32 + ((l & 16) ? 16 : 0);
                    ldsm_x4_t(bvn, smem_u32(cV + rowv * 512 + (cbyte ^ ((rowv & 7) << 4))));
                }
#pragma unroll
                for (int mt = 0; mt < 2; ++mt) {
                    mma_bf16(o[mt][ct * 2],     pA[mt], bv);
                    mma_bf16(o[mt][ct * 2 + 1], pA[mt], bv + 2);
                }
                if (ct < 3) { bv[0]=bvn[0]; bv[1]=bvn[1]; bv[2]=bvn[2]; bv[3]=bvn[3]; }
            }

            if (doqk) {
                const int nt = j >> 1, mt = j & 1;
                if ((j & 1) == 0) {
                    int n = qkNbase + nt * 8;
                    ldsm_x4(bk, smem_u32(cK1 + n * 64 + (qkCb ^ (((n >> 1) & 3) << 4))));
                }
                float s[4] = {0.f, 0.f, 0.f, 0.f};
                mma_bf16(s, aq[mt][0], bk);
                mma_bf16(s, aq[mt][1], bk + 2);
                s[0] = ex2f(s[0]); s[1] = ex2f(s[1]);
                s[2] = ex2f(s[2]); s[3] = ex2f(s[3]);
                li[mt][0] += s[0] + s[1];
                li[mt][1] += s[2] + s[3];
                int R0 = qkR0base + mt * 16, R1 = R0 + 8;
                int kb = qkKbase + nt * 16;
                int hi = kb & ~15, lo = kb & 15;
                *(uint32_t*)(sPn + R0 * 128 + ((hi ^ ((R0 & 7) << 4)) | lo)) =
                    packbf(s[0], s[1]);
                *(uint32_t*)(sPn + R1 * 128 + ((hi ^ ((R1 & 7) << 4)) | lo)) =
                    packbf(s[2], s[3]);
            }
        }
    }

#pragma unroll
    for (int mt = 0; mt < 2; ++mt)
#pragma unroll
        for (int h = 0; h < 2; ++h) {
            li[mt][h] += __shfl_xor_sync(0xffffffffu, li[mt][h], 1);
            li[mt][h] += __shfl_xor_sync(0xffffffffu, li[mt][h], 2);
        }
    if ((l & 3) == 0) {
#pragma unroll
        for (int mt = 0; mt < 2; ++mt)
#pragma unroll
            for (int h = 0; h < 2; ++h)
                sSum[(wr * 32 + mt * 16 + h * 8 + (l >> 2)) * 4 + wkc] = li[mt][h];
    }
    __syncthreads();

#pragma unroll
    for (int mt = 0; mt < 2; ++mt) {
        int r0 = wr * 32 + mt * 16 + (l >> 2);
        float4 s0 = *(float4*)(sSum + r0 * 4);
        float4 s1 = *(float4*)(sSum + (r0 + 8) * 4);
        float i0 = 1.f / (s0.x + s0.y + s0.z + s0.w);
        float i1 = 1.f / (s1.x + s1.y + s1.z + s1.w);
        int tok = m0 + r0;
#pragma unroll
        for (int nt = 0; nt < 8; ++nt) {
            int ch = wkc * 64 + nt * 8 + 2 * (l & 3);
            size_t base0 = ((size_t)(b * CCH + ch)) * NTOK + tok;
            size_t base1 = base0 + NTOK;
            out[base0]     = zin[base0]     + o[mt][nt][0] * i0;
            out[base1]     = zin[base1]     + o[mt][nt][1] * i0;
            out[base0 + 8] = zin[base0 + 8] + o[mt][nt][2] * i1;
            out[base1 + 8] = zin[base1 + 8] + o[mt][nt][3] * i1;
        }
    }
}

extern "C" void kernel_launch(void* const* d_in, const int* in_sizes, int n_in,
                              void* d_out, int out_size) {
    const float* z  = (const float*)d_in[0];
    const float* x  = (const float*)d_in[1];
    const float* y  = (const float*)d_in[2];
    const float* Wq = (const float*)d_in[3];
    const float* bq = (const float*)d_in[4];
    const float* Wk = (const float*)d_in[5];
    const float* bk = (const float*)d_in[6];
    const float* Wv = (const float*)d_in[7];
    const float* bv = (const float*)d_in[8];
    float* out = (float*)d_out;

    cudaFuncSetAttribute(proj_kernel, cudaFuncAttributeMaxDynamicSharedMemorySize,
                         PROJ_SMEM);
    cudaFuncSetAttribute(flash_kernel, cudaFuncAttributeMaxDynamicSharedMemorySize,
                         FLASH_SMEM);

    proj_kernel<<<dim3(64, 4, 3), 256, PROJ_SMEM>>>(z, x, y, Wq, bq, Wk, bk, Wv, bv);
    flash_kernel<<<dim3(32, 4), 512, FLASH_SMEM>>>(z, out);
}